// round 14
// baseline (speedup 1.0000x reference)
#include <cuda_runtime.h>
#include <math.h>

#define BB 16
#define T2 2048
#define T1 512
#define FD 128
#define WIN 3.0f
#define DELTA 10.0f
#define EPS 1e-8f
#define SG 8          // phonemes per align block
#define TCH 64        // frames per smem tile chunk

#define NPBLK 8192                    // propact blocks (2*BB*T2 warps / 8)
#define NSBLK BB                      // scan blocks
#define NABLK (BB * (T1 / SG))        // align blocks (1024)
#define ALIGN_PER_B (T1 / SG)         // 64

// ------------- scratch (device globals; no runtime allocation) -------------
__device__ long long g_prop[BB * T2]; // imv_proposal, fixed-point 2^32
__device__ float  g_act [BB * T2];    // activity * am
__device__ int    g_nvalid[BB];       // valid frame count per batch
// in-grid sync state (self-resetting each execution; zero-init at load)
__device__ unsigned g_c1;             // propact blocks done
__device__ unsigned g_c2;             // scan blocks done
__device__ int      g_flag[BB];       // per-batch "imv ready"
__device__ unsigned g_adone[BB];      // align blocks passed per batch

struct ScanSmem {
    float cum[T2];
    float wsum[8];
    int   red[256];
    float scale;
};
struct AlignSmem {
    float tile[TCH][FD];
    float w[TCH][SG];
    float D[SG];
    int   range[2];
};
union MegaSmem { ScanSmem scan; AlignSmem align; };

__global__ void __launch_bounds__(256, 6)
mega_kernel(const float* __restrict__ alpha,
            const float* __restrict__ mels,
            const int* __restrict__ mel_mask,
            const int* __restrict__ text_mask,
            float* __restrict__ aligned,
            float* __restrict__ durations,
            float* __restrict__ imv) {
    __shared__ MegaSmem sm;
    int bid = blockIdx.x;
    int tid = threadIdx.x;

    if (bid < NPBLK) {
        // ================= propact =================
        int warp = bid * 8 + (tid >> 5);
        int lane = tid & 31;
        if (warp < BB * T2) {
            const float* base = alpha + (size_t)warp * T1 + lane * 4;
            float a0,a1,a2,a3, b0,b1,b2,b3, c0,c1,c2,c3, d0,d1,d2,d3;
            asm("ld.global.nc.v4.f32 {%0,%1,%2,%3}, [%4];"
                : "=f"(a0), "=f"(a1), "=f"(a2), "=f"(a3) : "l"(base));
            asm("ld.global.nc.v4.f32 {%0,%1,%2,%3}, [%4];"
                : "=f"(b0), "=f"(b1), "=f"(b2), "=f"(b3) : "l"(base + 128));
            asm("ld.global.nc.v4.f32 {%0,%1,%2,%3}, [%4];"
                : "=f"(c0), "=f"(c1), "=f"(c2), "=f"(c3) : "l"(base + 256));
            asm("ld.global.nc.v4.f32 {%0,%1,%2,%3}, [%4];"
                : "=f"(d0), "=f"(d1), "=f"(d2), "=f"(d3) : "l"(base + 384));
            long long acc = 0;
            {
                float s = (float)(lane * 4);
                float p = a0 * s + a1 * (s + 1.0f) + a2 * (s + 2.0f) + a3 * (s + 3.0f);
                acc += __float2ll_rn(p * 4294967296.0f);
            }
            {
                float s = (float)((lane + 32) * 4);
                float p = b0 * s + b1 * (s + 1.0f) + b2 * (s + 2.0f) + b3 * (s + 3.0f);
                acc += __float2ll_rn(p * 4294967296.0f);
            }
            {
                float s = (float)((lane + 64) * 4);
                float p = c0 * s + c1 * (s + 1.0f) + c2 * (s + 2.0f) + c3 * (s + 3.0f);
                acc += __float2ll_rn(p * 4294967296.0f);
            }
            {
                float s = (float)((lane + 96) * 4);
                float p = d0 * s + d1 * (s + 1.0f) + d2 * (s + 2.0f) + d3 * (s + 3.0f);
                acc += __float2ll_rn(p * 4294967296.0f);
            }
#pragma unroll
            for (int o = 16; o; o >>= 1) acc += __shfl_down_sync(0xffffffffu, acc, o);
            if (lane == 0) g_prop[warp] = acc;
        } else {
            int w2 = warp - BB * T2;
            if (w2 < BB * T2) {
                int t = w2 & (T2 - 1);
                float am = (mel_mask[w2] != 0) ? 1.0f : 0.0f;
                if (t == 0) { if (lane == 0) g_act[w2] = am; }
                else {
                    const float4* r0 = (const float4*)(mels + (size_t)(w2 - 1) * FD);
                    const float4* r1 = (const float4*)(mels + (size_t)w2 * FD);
                    float4 a = r0[lane], b = r1[lane];
                    float dot = a.x * b.x + a.y * b.y + a.z * b.z + a.w * b.w;
                    float na  = a.x * a.x + a.y * a.y + a.z * a.z + a.w * a.w;
                    float nb  = b.x * b.x + b.y * b.y + b.z * b.z + b.w * b.w;
#pragma unroll
                    for (int o = 16; o; o >>= 1) {
                        dot += __shfl_down_sync(0xffffffffu, dot, o);
                        na  += __shfl_down_sync(0xffffffffu, na,  o);
                        nb  += __shfl_down_sync(0xffffffffu, nb,  o);
                    }
                    if (lane == 0) {
                        float n0 = fmaxf(sqrtf(na), 1e-12f);
                        float n1 = fmaxf(sqrtf(nb), 1e-12f);
                        float cs = dot / (n0 * n1);
                        float act = 1.0f / (1.0f + expf(-10.0f * (0.9f - cs)));
                        g_act[w2] = act * am;
                    }
                }
            }
        }
        __syncthreads();
        if (tid == 0) { __threadfence(); atomicAdd(&g_c1, 1u); }
        return;
    }

    if (bid < NPBLK + NSBLK) {
        // ================= scan (waits for all propact) =================
        int b = bid - NPBLK;
        if (tid == 0) {
            while (*(volatile unsigned*)&g_c1 < (unsigned)NPBLK) __nanosleep(64);
            __threadfence();
        }
        __syncthreads();

        int lane = tid & 31, wid = tid >> 5;
        int t0 = tid * 8;
        int gi0 = b * T2 + t0;

        longlong2 p01 = ((const longlong2*)(g_prop + gi0))[0];
        longlong2 p23 = ((const longlong2*)(g_prop + gi0))[1];
        longlong2 p45 = ((const longlong2*)(g_prop + gi0))[2];
        longlong2 p67 = ((const longlong2*)(g_prop + gi0))[3];
        float4 act03 = ((const float4*)(g_act + gi0))[0];
        float4 act47 = ((const float4*)(g_act + gi0))[1];
        int4 mm03 = ((const int4*)(mel_mask + gi0))[0];
        int4 mm47 = ((const int4*)(mel_mask + gi0))[1];
        long long pm1 = (t0 > 0) ? g_prop[gi0 - 1] : p01.x;

        long long pv[8] = { p01.x, p01.y, p23.x, p23.y, p45.x, p45.y, p67.x, p67.y };
        float av[8] = { act03.x, act03.y, act03.z, act03.w,
                        act47.x, act47.y, act47.z, act47.w };
        int mv[8] = { mm03.x, mm03.y, mm03.z, mm03.w, mm47.x, mm47.y, mm47.z, mm47.w };

        float vals[8];
        float run = 0.0f;
        int nv_local = 0;
#pragma unroll
        for (int i = 0; i < 8; i++) {
            int t = t0 + i;
            float eff = 0.0f;
            if (t > 0) {
                long long d = pv[i] - ((i == 0) ? pm1 : pv[i - 1]);
                float e = (float)d * 2.3283064365386963e-10f * av[i];
                eff = fminf(fmaxf(e, 0.0f), 1.0f);
            }
            run += eff;
            vals[i] = run;
            nv_local += (mv[i] != 0);
        }

        float ws = run;
#pragma unroll
        for (int o = 1; o < 32; o <<= 1) {
            float v = __shfl_up_sync(0xffffffffu, ws, o);
            if (lane >= o) ws += v;
        }
        if (lane == 31) sm.scan.wsum[wid] = ws;
        sm.scan.red[tid] = nv_local;
        __syncthreads();
        if (wid == 0 && lane < 8) {
            float v = sm.scan.wsum[lane];
#pragma unroll
            for (int o = 1; o < 8; o <<= 1) {
                float u = __shfl_up_sync(0xffu, v, o);
                if (lane >= o) v += u;
            }
            sm.scan.wsum[lane] = v;
        }
        for (int off = 128; off; off >>= 1) {
            __syncthreads();
            if (tid < off) sm.scan.red[tid] += sm.scan.red[tid + off];
        }
        __syncthreads();
        int nvalid = sm.scan.red[0];
        float offset = ((wid > 0) ? sm.scan.wsum[wid - 1] : 0.0f) + (ws - run);
#pragma unroll
        for (int i = 0; i < 8; i++) sm.scan.cum[t0 + i] = vals[i] + offset;
        __syncthreads();

        int tl = (text_mask[b * T1 + tid] != 0) + (text_mask[b * T1 + 256 + tid] != 0);
        sm.scan.red[tid] = tl;
        for (int off = 128; off; off >>= 1) {
            __syncthreads();
            if (tid < off) sm.scan.red[tid] += sm.scan.red[tid + off];
        }
        __syncthreads();
        if (tid == 0) {
            int text_len = sm.scan.red[0];
            int last_idx = max(nvalid - 1, 0);
            float aml = (mel_mask[b * T2 + last_idx] != 0) ? 1.0f : 0.0f;
            float last_val = fmaxf(sm.scan.cum[last_idx] * aml, 1e-6f);
            sm.scan.scale = fmaxf((float)text_len - 1.0f, 0.0f) / last_val;
            g_nvalid[b] = nvalid;
        }
        __syncthreads();
        float scale = sm.scan.scale;
#pragma unroll
        for (int i = 0; i < 8; i++) {
            int t = t0 + i;
            float am = (mv[i] != 0) ? 1.0f : 0.0f;
            imv[b * T2 + t] = sm.scan.cum[t] * am * scale;
        }
        __syncthreads();
        if (tid == 0) {
            __threadfence();
            atomicExch(&g_flag[b], 1);            // release imv for batch b
            unsigned r = atomicAdd(&g_c2, 1u);
            if (r == NSBLK - 1) {                 // last scan block: reset for next replay
                atomicExch(&g_c1, 0u);
                atomicExch(&g_c2, 0u);
            }
        }
        return;
    }

    // ================= align (waits for its batch's scan) =================
    {
        int idx = bid - NPBLK - NSBLK;
        int b  = idx >> 6;                        // idx / ALIGN_PER_B
        int sg = idx & (ALIGN_PER_B - 1);
        int s_base = sg * SG;
        int f = tid & 127;
        int half = tid >> 7;                      // 0/1: phonemes [0..3] / [4..7]

        if (tid == 0) {
            while (*(volatile int*)&g_flag[b] == 0) __nanosleep(64);
            __threadfence();
            unsigned r = atomicAdd(&g_adone[b], 1u);
            if (r == ALIGN_PER_B - 1) {           // last align block for b: reset
                atomicExch(&g_flag[b], 0);
                atomicExch(&g_adone[b], 0u);
            }
        }
        __syncthreads();

        const float* imvb = imv + b * T2;
        if (tid == 0) {
            int n = g_nvalid[b];
            float lo = (float)s_base - WIN;
            float hi = (float)(s_base + SG - 1) + WIN;
            int a = 0, c = n;
            while (a < c) { int m = (a + c) >> 1; if (imvb[m] < lo) a = m + 1; else c = m; }
            sm.align.range[0] = a;
            int a2 = a, c2 = n;
            while (a2 < c2) { int m = (a2 + c2) >> 1; if (imvb[m] <= hi) a2 = m + 1; else c2 = m; }
            sm.align.range[1] = a2;
        }
        if (tid < SG) sm.align.D[tid] = 0.0f;
        __syncthreads();

        int t0 = sm.align.range[0], t1 = sm.align.range[1];
        float acc4[4] = {0.0f, 0.0f, 0.0f, 0.0f};
        int row8 = tid >> 5;                      // 0..7
        int quad = tid & 31;

        for (int base = t0; base < t1; base += TCH) {
            int nt = min(TCH, t1 - base);
            __syncthreads();                      // prior chunk fully consumed

            // fire tile copies: 8 rows per step, 256 threads
            {
                const float* src0 = mels + ((size_t)(b * T2 + base + row8)) * FD + quad * 4;
#pragma unroll
                for (int k = 0; k < TCH / 8; k++) {
                    int row = row8 + k * 8;
                    if (row < nt) {
                        unsigned smp = (unsigned)__cvta_generic_to_shared(&sm.align.tile[row][quad * 4]);
                        asm volatile("cp.async.cg.shared.global [%0], [%1], 16;"
                                     :: "r"(smp), "l"(src0 + (size_t)k * 8 * FD));
                    }
                }
                asm volatile("cp.async.commit_group;");
            }

            // weight phase (threads 0..nt-1) overlaps the copies
            if (tid < nt) {
                int t = base + tid;
                int gi = b * T2 + t;
                float w8[SG];
#pragma unroll
                for (int si = 0; si < SG; si++) w8[si] = 0.0f;
                if (mel_mask[gi]) {
                    float v = imvb[t];
                    int z0 = max(0, (int)ceilf(v - WIN));
                    int z1 = min(T1 - 1, (int)floorf(v + WIN));
                    float Z = 0.0f;
                    for (int sp = z0; sp <= z1; sp++) {
                        if (text_mask[b * T1 + sp]) {
                            float dz = v - (float)sp;
                            Z += expf(-DELTA * dz * dz);
                        }
                    }
                    if (Z > 0.0f) {
                        float inv = 1.0f / Z;
#pragma unroll
                        for (int si = 0; si < SG; si++) {
                            float d = v - (float)(s_base + si);
                            w8[si] = expf(-DELTA * d * d) * inv;
                        }
                    }
                }
#pragma unroll
                for (int si = 0; si < SG; si++) sm.align.w[tid][si] = w8[si];
            }

            asm volatile("cp.async.wait_group 0;" ::: "memory");
            __syncthreads();

            if (tid < SG) {
                float d = 0.0f;
                for (int j = 0; j < nt; j++) d += sm.align.w[j][tid];
                sm.align.D[tid] += d;
            }

            // accumulation: each half does 4 FMAs per tile element
            for (int j = 0; j < nt; j++) {
                float m = sm.align.tile[j][f];
                float4 w4 = *(const float4*)&sm.align.w[j][half * 4];
                acc4[0] += w4.x * m; acc4[1] += w4.y * m;
                acc4[2] += w4.z * m; acc4[3] += w4.w * m;
            }
        }
        __syncthreads();

#pragma unroll
        for (int k = 0; k < 4; k++) {
            int s = s_base + half * 4 + k;
            int tm = text_mask[b * T1 + s];
            float D = sm.align.D[half * 4 + k];
            aligned[((size_t)(b * T1 + s)) * FD + f] = tm ? (acc4[k] / (D + EPS)) : 0.0f;
        }
        if (tid < SG) {
            int s = s_base + tid;
            durations[b * T1 + s] = text_mask[b * T1 + s] ? sm.align.D[tid] : 0.0f;
        }
    }
}

// ------------- launch ------------------------------------------------------
extern "C" void kernel_launch(void* const* d_in, const int* in_sizes, int n_in,
                              void* d_out, int out_size) {
    const float* mels      = (const float*)d_in[0];  // [B,T2,F]
    const float* alpha     = (const float*)d_in[1];  // [B,T2,T1]
    const int*   mel_mask  = (const int*)d_in[2];    // [B,T2]
    const int*   text_mask = (const int*)d_in[3];    // [B,T1]

    float* out       = (float*)d_out;
    float* aligned   = out;                              // B*T1*F
    float* durations = out + (size_t)BB * T1 * FD;       // B*T1
    float* imv       = durations + (size_t)BB * T1;      // B*T2

    mega_kernel<<<NPBLK + NSBLK + NABLK, 256>>>(alpha, mels, mel_mask, text_mask,
                                                aligned, durations, imv);
}

// round 15
// speedup vs baseline: 1.2536x; 1.2536x over previous
#include <cuda_runtime.h>
#include <math.h>

#define BB 16
#define T2 2048
#define T1 512
#define FD 128
#define WIN 3.0f
#define DELTA 10.0f
#define EPS 1e-8f
#define SG 8          // phonemes per align block
#define TCH 64        // frames per smem tile chunk

// ------------- scratch (device globals; no runtime allocation) -------------
__device__ long long g_prop[BB * T2]; // imv_proposal, fixed-point 2^32
__device__ float  g_act [BB * T2];    // activity * am
__device__ int    g_nvalid[BB];       // valid frame count per batch

// ------------- kernel A: fused prop + act (R7/R12 config) -----------------
__global__ void propact_kernel(const float* __restrict__ alpha,
                               const float* __restrict__ mels,
                               const int* __restrict__ mel_mask) {
    int warp = (blockIdx.x * blockDim.x + threadIdx.x) >> 5;
    int lane = threadIdx.x & 31;

    if (warp < BB * T2) {
        const float* base = alpha + (size_t)warp * T1 + lane * 4;
        float a0,a1,a2,a3, b0,b1,b2,b3, c0,c1,c2,c3, d0,d1,d2,d3;
        asm("ld.global.nc.v4.f32 {%0,%1,%2,%3}, [%4];"
            : "=f"(a0), "=f"(a1), "=f"(a2), "=f"(a3) : "l"(base));
        asm("ld.global.nc.v4.f32 {%0,%1,%2,%3}, [%4];"
            : "=f"(b0), "=f"(b1), "=f"(b2), "=f"(b3) : "l"(base + 128));
        asm("ld.global.nc.v4.f32 {%0,%1,%2,%3}, [%4];"
            : "=f"(c0), "=f"(c1), "=f"(c2), "=f"(c3) : "l"(base + 256));
        asm("ld.global.nc.v4.f32 {%0,%1,%2,%3}, [%4];"
            : "=f"(d0), "=f"(d1), "=f"(d2), "=f"(d3) : "l"(base + 384));
        long long acc = 0;
        {
            float s = (float)(lane * 4);
            float p = a0 * s + a1 * (s + 1.0f) + a2 * (s + 2.0f) + a3 * (s + 3.0f);
            acc += __float2ll_rn(p * 4294967296.0f);
        }
        {
            float s = (float)((lane + 32) * 4);
            float p = b0 * s + b1 * (s + 1.0f) + b2 * (s + 2.0f) + b3 * (s + 3.0f);
            acc += __float2ll_rn(p * 4294967296.0f);
        }
        {
            float s = (float)((lane + 64) * 4);
            float p = c0 * s + c1 * (s + 1.0f) + c2 * (s + 2.0f) + c3 * (s + 3.0f);
            acc += __float2ll_rn(p * 4294967296.0f);
        }
        {
            float s = (float)((lane + 96) * 4);
            float p = d0 * s + d1 * (s + 1.0f) + d2 * (s + 2.0f) + d3 * (s + 3.0f);
            acc += __float2ll_rn(p * 4294967296.0f);
        }
#pragma unroll
        for (int o = 16; o; o >>= 1) acc += __shfl_down_sync(0xffffffffu, acc, o);
        if (lane == 0) g_prop[warp] = acc;
    } else {
        int w2 = warp - BB * T2;
        if (w2 >= BB * T2) {
#if __CUDA_ARCH__ >= 900
            cudaTriggerProgrammaticLaunchCompletion();
#endif
            return;
        }
        int t = w2 & (T2 - 1);
        float am = (mel_mask[w2] != 0) ? 1.0f : 0.0f;
        if (t == 0) { if (lane == 0) g_act[w2] = am; }
        else {
            const float4* r0 = (const float4*)(mels + (size_t)(w2 - 1) * FD);
            const float4* r1 = (const float4*)(mels + (size_t)w2 * FD);
            float4 a = r0[lane], b = r1[lane];
            float dot = a.x * b.x + a.y * b.y + a.z * b.z + a.w * b.w;
            float na  = a.x * a.x + a.y * a.y + a.z * a.z + a.w * a.w;
            float nb  = b.x * b.x + b.y * b.y + b.z * b.z + b.w * b.w;
#pragma unroll
            for (int o = 16; o; o >>= 1) {
                dot += __shfl_down_sync(0xffffffffu, dot, o);
                na  += __shfl_down_sync(0xffffffffu, na,  o);
                nb  += __shfl_down_sync(0xffffffffu, nb,  o);
            }
            if (lane == 0) {
                float n0 = fmaxf(sqrtf(na), 1e-12f);
                float n1 = fmaxf(sqrtf(nb), 1e-12f);
                float cs = dot / (n0 * n1);
                float act = 1.0f / (1.0f + expf(-10.0f * (0.9f - cs)));
                g_act[w2] = act * am;
            }
        }
    }
#if __CUDA_ARCH__ >= 900
    cudaTriggerProgrammaticLaunchCompletion();
#endif
}

// ------------- kernel B: per-batch gated cumsum + rescale -> imv ----------
__global__ void scan_kernel(const int* __restrict__ mel_mask,
                            const int* __restrict__ text_mask,
                            float* __restrict__ imv_out) {
    int b = blockIdx.x;
    int tid = threadIdx.x;                 // 256 threads, 8 elems each
    int lane = tid & 31, wid = tid >> 5;   // 8 warps
    __shared__ float s_cum[T2];
    __shared__ float s_wsum[8];
    __shared__ int   s_red[256];
    __shared__ float s_scale;

    int t0 = tid * 8;
    int gi0 = b * T2 + t0;

    // independent of propact: text_mask reduction prep can overlap
    int tl = (text_mask[b * T1 + tid] != 0) + (text_mask[b * T1 + 256 + tid] != 0);
    int4 mm03 = ((const int4*)(mel_mask + gi0))[0];
    int4 mm47 = ((const int4*)(mel_mask + gi0))[1];

#if __CUDA_ARCH__ >= 900
    cudaGridDependencySynchronize();       // wait for propact results
#endif

    longlong2 p01 = ((const longlong2*)(g_prop + gi0))[0];
    longlong2 p23 = ((const longlong2*)(g_prop + gi0))[1];
    longlong2 p45 = ((const longlong2*)(g_prop + gi0))[2];
    longlong2 p67 = ((const longlong2*)(g_prop + gi0))[3];
    float4 act03 = ((const float4*)(g_act + gi0))[0];
    float4 act47 = ((const float4*)(g_act + gi0))[1];
    long long pm1 = (t0 > 0) ? g_prop[gi0 - 1] : p01.x;  // prop[t0-1]

    long long pv[8] = { p01.x, p01.y, p23.x, p23.y, p45.x, p45.y, p67.x, p67.y };
    float av[8] = { act03.x, act03.y, act03.z, act03.w,
                    act47.x, act47.y, act47.z, act47.w };
    int mv[8] = { mm03.x, mm03.y, mm03.z, mm03.w, mm47.x, mm47.y, mm47.z, mm47.w };

    float vals[8];
    float run = 0.0f;
    int nv_local = 0;
#pragma unroll
    for (int i = 0; i < 8; i++) {
        int t = t0 + i;
        float eff = 0.0f;
        if (t > 0) {
            long long d = pv[i] - ((i == 0) ? pm1 : pv[i - 1]);
            float e = (float)d * 2.3283064365386963e-10f * av[i]; // * 2^-32
            eff = fminf(fmaxf(e, 0.0f), 1.0f);
        }
        run += eff;
        vals[i] = run;
        nv_local += (mv[i] != 0);
    }

    float ws = run;
#pragma unroll
    for (int o = 1; o < 32; o <<= 1) {
        float v = __shfl_up_sync(0xffffffffu, ws, o);
        if (lane >= o) ws += v;
    }
    if (lane == 31) s_wsum[wid] = ws;
    s_red[tid] = nv_local;
    __syncthreads();
    if (wid == 0 && lane < 8) {
        float v = s_wsum[lane];
#pragma unroll
        for (int o = 1; o < 8; o <<= 1) {
            float u = __shfl_up_sync(0xffu, v, o);
            if (lane >= o) v += u;
        }
        s_wsum[lane] = v;
    }
    for (int off = 128; off; off >>= 1) {
        __syncthreads();
        if (tid < off) s_red[tid] += s_red[tid + off];
    }
    __syncthreads();
    int nvalid = s_red[0];
    float offset = ((wid > 0) ? s_wsum[wid - 1] : 0.0f) + (ws - run);
#pragma unroll
    for (int i = 0; i < 8; i++) s_cum[t0 + i] = vals[i] + offset;
    __syncthreads();

    s_red[tid] = tl;
    for (int off = 128; off; off >>= 1) {
        __syncthreads();
        if (tid < off) s_red[tid] += s_red[tid + off];
    }
    __syncthreads();
    if (tid == 0) {
        int text_len = s_red[0];
        int last_idx = max(nvalid - 1, 0);
        float aml = (mel_mask[b * T2 + last_idx] != 0) ? 1.0f : 0.0f;
        float last_val = fmaxf(s_cum[last_idx] * aml, 1e-6f);
        float scale = fmaxf((float)text_len - 1.0f, 0.0f) / last_val;
        s_scale = scale;
        g_nvalid[b] = nvalid;
    }
    __syncthreads();
    float scale = s_scale;
#pragma unroll
    for (int i = 0; i < 8; i++) {
        int t = t0 + i;
        float am = (mv[i] != 0) ? 1.0f : 0.0f;
        imv_out[b * T2 + t] = s_cum[t] * am * scale;
    }
#if __CUDA_ARCH__ >= 900
    cudaTriggerProgrammaticLaunchCompletion();
#endif
}

// ------------- kernel C: grouped align, cp.async tile staging -------------
__global__ void align_kernel(const float* __restrict__ mels,
                             const int* __restrict__ mel_mask,
                             const int* __restrict__ text_mask,
                             const float* __restrict__ imv,
                             float* __restrict__ aligned,
                             float* __restrict__ durations) {
    int sg = blockIdx.x;
    int b  = blockIdx.y;
    int s_base = sg * SG;
    int f = threadIdx.x;                      // 128 threads == FD
    __shared__ float tile[TCH][FD];           // 32 KB mel tile
    __shared__ float s_w[TCH][SG];            // 2 KB weight matrix
    __shared__ float s_D[SG];
    __shared__ int s_range[2];

    if (f < SG) s_D[f] = 0.0f;

#if __CUDA_ARCH__ >= 900
    cudaGridDependencySynchronize();          // wait for imv / g_nvalid
#endif

    const float* imvb = imv + b * T2;
    if (f == 0) {
        int n = g_nvalid[b];
        float lo = (float)s_base - WIN;
        float hi = (float)(s_base + SG - 1) + WIN;
        int a = 0, c = n;
        while (a < c) { int m = (a + c) >> 1; if (imvb[m] < lo) a = m + 1; else c = m; }
        s_range[0] = a;
        int a2 = a, c2 = n;
        while (a2 < c2) { int m = (a2 + c2) >> 1; if (imvb[m] <= hi) a2 = m + 1; else c2 = m; }
        s_range[1] = a2;
    }
    __syncthreads();

    int t0 = s_range[0], t1 = s_range[1];
    float acc[SG];
#pragma unroll
    for (int si = 0; si < SG; si++) acc[si] = 0.0f;

    int row4 = f >> 5;      // 0..3: row within 4-row group
    int quad = f & 31;      // float4 column within row

    for (int base = t0; base < t1; base += TCH) {
        int nt = min(TCH, t1 - base);
        __syncthreads();                       // prior chunk fully consumed

        // ---- fire all tile copies via cp.async (4 rows per group) ----
        {
            const float* src0 = mels + ((size_t)(b * T2 + base + row4)) * FD + quad * 4;
#pragma unroll
            for (int k = 0; k < TCH / 4; k++) {
                int row = row4 + k * 4;
                if (row < nt) {
                    unsigned smp = (unsigned)__cvta_generic_to_shared(&tile[row][quad * 4]);
                    asm volatile("cp.async.cg.shared.global [%0], [%1], 16;"
                                 :: "r"(smp), "l"(src0 + (size_t)k * 4 * FD));
                }
            }
            asm volatile("cp.async.commit_group;");
        }

        // ---- weight phase overlaps the copies ----
        if (f < nt) {
            int t = base + f;
            int gi = b * T2 + t;
            float w8[SG];
#pragma unroll
            for (int si = 0; si < SG; si++) w8[si] = 0.0f;
            if (mel_mask[gi]) {
                float v = imvb[t];
                int z0 = max(0, (int)ceilf(v - WIN));
                int z1 = min(T1 - 1, (int)floorf(v + WIN));
                float Z = 0.0f;
                for (int sp = z0; sp <= z1; sp++) {
                    if (text_mask[b * T1 + sp]) {
                        float dz = v - (float)sp;
                        Z += expf(-DELTA * dz * dz);
                    }
                }
                if (Z > 0.0f) {
                    float inv = 1.0f / Z;
#pragma unroll
                    for (int si = 0; si < SG; si++) {
                        float d = v - (float)(s_base + si);
                        w8[si] = expf(-DELTA * d * d) * inv;
                    }
                }
            }
#pragma unroll
            for (int si = 0; si < SG; si++) s_w[f][si] = w8[si];
        }

        asm volatile("cp.async.wait_group 0;" ::: "memory");
        __syncthreads();

        // ---- D accumulation (one thread per phoneme) ----
        if (f < SG) {
            float d = 0.0f;
            for (int j = 0; j < nt; j++) d += s_w[j][f];
            s_D[f] += d;
        }

        // ---- main accumulation: 8 FMAs per tile element ----
        for (int j = 0; j < nt; j++) {
            float m = tile[j][f];
            float4 wa = *(const float4*)&s_w[j][0];
            float4 wb = *(const float4*)&s_w[j][4];
            acc[0] += wa.x * m; acc[1] += wa.y * m;
            acc[2] += wa.z * m; acc[3] += wa.w * m;
            acc[4] += wb.x * m; acc[5] += wb.y * m;
            acc[6] += wb.z * m; acc[7] += wb.w * m;
        }
    }
    __syncthreads();

#pragma unroll
    for (int si = 0; si < SG; si++) {
        int s = s_base + si;
        int tm = text_mask[b * T1 + s];
        float D = s_D[si];
        aligned[((size_t)(b * T1 + s)) * FD + f] = tm ? (acc[si] / (D + EPS)) : 0.0f;
    }
    if (f < SG) {
        int s = s_base + f;
        durations[b * T1 + s] = text_mask[b * T1 + s] ? s_D[f] : 0.0f;
    }
}

// ------------- launch ------------------------------------------------------
extern "C" void kernel_launch(void* const* d_in, const int* in_sizes, int n_in,
                              void* d_out, int out_size) {
    const float* mels      = (const float*)d_in[0];  // [B,T2,F]
    const float* alpha     = (const float*)d_in[1];  // [B,T2,T1]
    const int*   mel_mask  = (const int*)d_in[2];    // [B,T2]
    const int*   text_mask = (const int*)d_in[3];    // [B,T1]

    float* out       = (float*)d_out;
    float* aligned   = out;                              // B*T1*F
    float* durations = out + (size_t)BB * T1 * FD;       // B*T1
    float* imv       = durations + (size_t)BB * T1;      // B*T2

    int nwarp = 2 * BB * T2;                             // prop + act warps
    int nblk  = (nwarp * 32 + 255) / 256;

    propact_kernel<<<nblk, 256>>>(alpha, mels, mel_mask);

    cudaLaunchAttribute attr[1];
    attr[0].id = cudaLaunchAttributeProgrammaticStreamSerialization;
    attr[0].val.programmaticStreamSerializationAllowed = 1;

    {
        cudaLaunchConfig_t cfg = {};
        cfg.gridDim = dim3(BB, 1, 1);
        cfg.blockDim = dim3(256, 1, 1);
        cfg.stream = 0;
        cfg.attrs = attr;
        cfg.numAttrs = 1;
        cudaLaunchKernelEx(&cfg, scan_kernel, mel_mask, text_mask, imv);
    }
    {
        cudaLaunchConfig_t cfg = {};
        cfg.gridDim = dim3(T1 / SG, BB, 1);
        cfg.blockDim = dim3(FD, 1, 1);
        cfg.stream = 0;
        cfg.attrs = attr;
        cfg.numAttrs = 1;
        cudaLaunchKernelEx(&cfg, align_kernel, mels, mel_mask, text_mask,
                           imv, aligned, durations);
    }
}